// round 15
// baseline (speedup 1.0000x reference)
#include <cuda_runtime.h>
#include <cuda_fp16.h>
#include <cstdint>
#include <math.h>

#define BATCH 8
#define TLEN 512
#define EDIM 512
#define HDIM 1024
#define VDIM 32000
#define NL 6
#define MTOT (BATCH*TLEN)
#define SCALE 0.7071067811865476f

// ===========================================================================
// Scratch carve-out (bytes)
// ===========================================================================
constexpr unsigned long long
 oEMBF  = 0ull,
 oXPADF = oEMBF  + 8388608ull,
 oCONVF = oXPADF + 16842752ull,
 oGLUF  = oCONVF + 33554432ull,
 oATTNF = oGLUF  + 16777216ull,
 oEMBH  = oATTNF + 8388608ull,
 oEMBL  = oEMBH  + 4194304ull,
 oXPADH = oEMBL  + 4194304ull,
 oXPADL = oXPADH + 8421376ull,
 oGLUH  = oXPADL + 8421376ull,
 oGLUL  = oGLUH  + 8388608ull,
 oCOMBH = oGLUL  + 8388608ull,
 oCOMBL = oCOMBH + 4194304ull,
 oATTNH = oCOMBL + 4194304ull,
 oATTNL = oATTNH + 4194304ull,
 oATTH  = oATTNL + 4194304ull,
 oATTL  = oATTH  + 4194304ull,
 oCOUTH = oATTL  + 4194304ull,
 oCOUTL = oCOUTH + 4194304ull,
 oWTH   = oCOUTL + 4194304ull,
 oWTL   = oWTH   + 12582912ull,
 oW1H   = oWTL   + 12582912ull,
 oW1L   = oW1H   + 1048576ull,
 oW2H   = oW1L   + 1048576ull,
 oW2L   = oW2H   + 1048576ull,
 oW3H   = oW2L   + 1048576ull,
 oW3L   = oW3H   + 1048576ull,
 oW4H   = oW3L   + 1048576ull,
 oW4L   = oW4H   + 1048576ull,
 oWFCH  = oW4L   + 1048576ull,
 oWFCL  = oWFCH  + 32768000ull,
 oENCVH = oWFCL  + 32768000ull,
 oENCVL = oENCVH + 4194304ull,
 oENCTH = oENCVL + 4194304ull,
 oENCTL = oENCTH + 4194304ull,
 G_TOTAL = oENCTL + 4194304ull;

__device__ __align__(1024) unsigned char g_mem[G_TOTAL];

// ===========================================================================
// PTX helpers (arch-agnostic: cp.async + ldmatrix + mma.sync fp16)
// ===========================================================================
__device__ __forceinline__ uint32_t smem_u32(const void* p) {
    uint32_t a;
    asm("{ .reg .u64 t; cvta.to.shared.u64 t, %1; cvt.u32.u64 %0, t; }" : "=r"(a) : "l"(p));
    return a;
}
#define CP16(dst, src) asm volatile("cp.async.cg.shared.global [%0], [%1], 16;" :: "r"(dst), "l"(src))
#define CP_COMMIT()    asm volatile("cp.async.commit_group;" ::: "memory")
template<int N> __device__ __forceinline__ void cp_wait() {
    asm volatile("cp.async.wait_group %0;" :: "n"(N) : "memory");
}
__device__ __forceinline__ void ldsm4(uint32_t* d, uint32_t a) {
    asm volatile("ldmatrix.sync.aligned.m8n8.x4.shared.b16 {%0,%1,%2,%3}, [%4];"
        : "=r"(d[0]), "=r"(d[1]), "=r"(d[2]), "=r"(d[3]) : "r"(a));
}
__device__ __forceinline__ void mma16816(float* c, const uint32_t* a, const uint32_t* b) {
    asm volatile("mma.sync.aligned.m16n8k16.row.col.f32.f16.f16.f32 "
        "{%0,%1,%2,%3}, {%4,%5,%6,%7}, {%8,%9}, {%0,%1,%2,%3};"
        : "+f"(c[0]), "+f"(c[1]), "+f"(c[2]), "+f"(c[3])
        : "r"(a[0]), "r"(a[1]), "r"(a[2]), "r"(a[3]), "r"(b[0]), "r"(b[1]));
}

__device__ __forceinline__ void store_split4(__half* ph, __half* pl, float4 v) {
    __half h0 = __float2half_rn(v.x), h1 = __float2half_rn(v.y);
    __half h2 = __float2half_rn(v.z), h3 = __float2half_rn(v.w);
    __half2 a; a.x = h0; a.y = h1;
    __half2 b; b.x = h2; b.y = h3;
    *(__half2*)(ph) = a; *(__half2*)(ph + 2) = b;
    __half2 c, d;
    c.x = __float2half_rn(v.x - __half2float(h0));
    c.y = __float2half_rn(v.y - __half2float(h1));
    d.x = __float2half_rn(v.z - __half2float(h2));
    d.y = __float2half_rn(v.w - __half2float(h3));
    *(__half2*)(pl) = c; *(__half2*)(pl + 2) = d;
}
__device__ __forceinline__ void store_split2(__half* ph, __half* pl, float x, float y) {
    __half h0 = __float2half_rn(x), h1 = __float2half_rn(y);
    __half2 a; a.x = h0; a.y = h1;
    *(__half2*)(ph) = a;
    __half2 c;
    c.x = __float2half_rn(x - __half2float(h0));
    c.y = __float2half_rn(y - __half2float(h1));
    *(__half2*)(pl) = c;
}

// ===========================================================================
// Elementwise / prep kernels
// ===========================================================================
__global__ void embed_kernel(const int* __restrict__ trg, const float* __restrict__ tok,
                             const float* __restrict__ pos, float* __restrict__ out,
                             __half* __restrict__ oh, __half* __restrict__ ol) {
    int m = blockIdx.x, t = m & (TLEN - 1), i = threadIdx.x;
    long long tokid = trg[m];
    float4 a = ((const float4*)(tok + tokid * EDIM))[i];
    float4 b = ((const float4*)(pos + (long long)t * EDIM))[i];
    float4 v = make_float4(a.x + b.x, a.y + b.y, a.z + b.z, a.w + b.w);
    ((float4*)(out + (long long)m * EDIM))[i] = v;
    long long o = (long long)m * EDIM + i * 4;
    store_split4(oh + o, ol + o, v);
}

__global__ void pad_kernel(float* __restrict__ xp, __half* __restrict__ xh,
                           __half* __restrict__ xl) {
    int i = blockIdx.x * blockDim.x + threadIdx.x;
    int b = i >> 11, r = i & 2047;
    long long o = (long long)b * 514 * 1024 + r;
    xp[o] = 1.0f; xh[o] = __float2half_rn(1.0f); xl[o] = __float2half_rn(0.0f);
}

__global__ void glu_kernel(const float* __restrict__ conved, float* __restrict__ out,
                           __half* __restrict__ oh, __half* __restrict__ ol) {
    long long idx = (long long)blockIdx.x * blockDim.x + threadIdx.x;
    long long m = idx >> 10;
    int j = (int)(idx & 1023);
    float a = conved[m * 2048 + j];
    float g = conved[m * 2048 + 1024 + j];
    float v = a * (1.0f / (1.0f + expf(-g)));
    out[idx] = v;
    __half h = __float2half_rn(v);
    oh[idx] = h;
    ol[idx] = __float2half_rn(v - __half2float(h));
}

__global__ void softmax_kernel(const float* __restrict__ attn,
                               __half* __restrict__ oh, __half* __restrict__ ol) {
    long long row = blockIdx.x;
    const float4* p = (const float4*)(attn + row * 512);
    float4 v = p[threadIdx.x];
    float mx = fmaxf(fmaxf(v.x, v.y), fmaxf(v.z, v.w));
    #pragma unroll
    for (int s = 16; s; s >>= 1) mx = fmaxf(mx, __shfl_xor_sync(0xffffffffu, mx, s));
    __shared__ float sm[4], ss[4];
    int w = threadIdx.x >> 5;
    if ((threadIdx.x & 31) == 0) sm[w] = mx;
    __syncthreads();
    mx = fmaxf(fmaxf(sm[0], sm[1]), fmaxf(sm[2], sm[3]));
    v.x = expf(v.x - mx); v.y = expf(v.y - mx);
    v.z = expf(v.z - mx); v.w = expf(v.w - mx);
    float sum = v.x + v.y + v.z + v.w;
    #pragma unroll
    for (int s = 16; s; s >>= 1) sum += __shfl_xor_sync(0xffffffffu, sum, s);
    if ((threadIdx.x & 31) == 0) ss[w] = sum;
    __syncthreads();
    float inv = 1.0f / (ss[0] + ss[1] + ss[2] + ss[3]);
    v.x *= inv; v.y *= inv; v.z *= inv; v.w *= inv;
    long long o = row * 512 + threadIdx.x * 4;
    store_split4(oh + o, ol + o, v);
}

__global__ void split_kernel(const float* __restrict__ in, __half* __restrict__ oh,
                             __half* __restrict__ ol, long long n) {
    long long idx = (long long)blockIdx.x * blockDim.x + threadIdx.x;
    if (idx >= n) return;
    float v = in[idx];
    __half h = __float2half_rn(v);
    oh[idx] = h;
    ol[idx] = __float2half_rn(v - __half2float(h));
}

// fp32 (R,C) -> fp16 hi/lo (C,R), batched by blockIdx.z
__global__ void transpose_split_kernel(const float* __restrict__ in,
                                       __half* __restrict__ oh,
                                       __half* __restrict__ ol,
                                       int R, int C, long long bat) {
    __shared__ float t[32][33];
    in += blockIdx.z * bat; oh += blockIdx.z * bat; ol += blockIdx.z * bat;
    int c0 = blockIdx.x * 32, r0 = blockIdx.y * 32;
    int tx = threadIdx.x, ty = threadIdx.y;
    for (int ry = ty; ry < 32; ry += 8)
        t[ry][tx] = in[(long long)(r0 + ry) * C + c0 + tx];
    __syncthreads();
    for (int ry = ty; ry < 32; ry += 8) {
        float v = t[tx][ry];
        long long o = (long long)(c0 + ry) * R + r0 + tx;
        __half h = __float2half_rn(v);
        oh[o] = h;
        ol[o] = __float2half_rn(v - __half2float(h));
    }
}

// conv_w layer (2H,H,K): row o contiguous (i,kk); out[o][kk*1024+i], split.
__global__ void convw_split_kernel(const float* __restrict__ w,
                                   __half* __restrict__ oh,
                                   __half* __restrict__ ol) {
    __shared__ float row[3072];
    long long o = blockIdx.x;
    for (int x = threadIdx.x; x < 3072; x += 256) row[x] = w[o * 3072 + x];
    __syncthreads();
    for (int y = threadIdx.x; y < 3072; y += 256) {
        int i = y & 1023, kk = y >> 10;
        float v = row[i * 3 + kk];
        __half h = __float2half_rn(v);
        oh[o * 3072 + y] = h;
        ol[o * 3072 + y] = __float2half_rn(v - __half2float(h));
    }
}

// ===========================================================================
// mma.sync fp16-split GEMM: C(256x128 tile) = epi( A(M,K) @ B(N,K)^T )
//   NPASS=3: Ah*Bh + Ah*Bl + Al*Bh   (error ~ eps_fp16^2)
//   NPASS=2: Ah*Bh + Ah*Bl           (A rounded; error ~ eps_fp16/sqrt(3))
//   NPASS=1: Ah*Bh                   (both rounded; use only deeply damped)
//   Skips unneeded lo loads per NPASS.
//   256 threads, 8 warps (4x2 -> 64x64 per warp), BK=32, 3-stage cp.async.
//   Smem rows padded to 40 halves (80B) -> conflict-free ldmatrix.
//   AMAP: 0 row m*lda ; 1 conv map (m+2b)*1024 ; 2 token map (m+2b+2)*1024
//   CMAP: 0 m*N ; 1 xpad interior
//   EPI : 0 +bias ; 1 (acc+b+add1)*S ; 2 ((acc+b+add1)*S+Cold)*S ; 3 plain
//   OUT : 0 fp32 ; 1 fp32+split ; 2 split only
// ===========================================================================
constexpr int A_OPB  = 256 * 80;               // 20480 B per A operand
constexpr int B_OPB  = 128 * 80;               // 10240 B per B operand
constexpr int STAGE  = 2 * A_OPB + 2 * B_OPB;  // 61440
constexpr int GSMEM  = 3 * STAGE;              // 184320

template<int AMAP, int CMAP, int EPI, int OUT, int NPASS>
__global__ __launch_bounds__(256, 1) void tgemm(
    const __half* __restrict__ Ahi, const __half* __restrict__ Alo,
    const __half* __restrict__ Bhi, const __half* __restrict__ Blo,
    const float* __restrict__ bias, const float* __restrict__ add1,
    float* __restrict__ C, __half* __restrict__ Chi, __half* __restrict__ Clo,
    int N, int Kd, int lda, long long batA, long long batB, long long batC)
{
    extern __shared__ __align__(128) char smem[];
    const uint32_t sb = smem_u32(smem);
    const int tid = threadIdx.x;
    const int lane = tid & 31, wid = tid >> 5;
    const int m0 = blockIdx.y * 256, n0 = blockIdx.x * 128;
    const int wm = (wid >> 1) * 64, wn = (wid & 1) * 64;
    {
        long long z = blockIdx.z;
        Ahi += z * batA; Alo += z * batA;
        Bhi += z * batB; Blo += z * batB;
        if (OUT != 2) C += z * batC;
        if (OUT >= 1) { Chi += z * batC; Clo += z * batC; }
    }

    float acc[4][8][4];
    #pragma unroll
    for (int a = 0; a < 4; a++)
        #pragma unroll
        for (int b = 0; b < 8; b++)
            #pragma unroll
            for (int c = 0; c < 4; c++) acc[a][b][c] = 0.0f;

    const int nch = Kd >> 5;   // BK = 32

    auto load_chunk = [&](int j) {
        uint32_t st = sb + (j % 3) * STAGE;
        int k0 = j * 32;
        #pragma unroll
        for (int i2 = 0; i2 < 4; i2++) {      // A: 1024 16B-segs per operand
            int sidx = i2 * 256 + tid;
            int r = sidx >> 2, sg = sidx & 3;
            uint32_t soff = r * 80 + sg * 16;
            int gm = m0 + r;
            long long ab;
            if (AMAP == 0)      ab = (long long)gm * lda;
            else if (AMAP == 1) ab = (long long)(gm + 2 * (gm >> 9)) * 1024;
            else                ab = (long long)(gm + 2 * (gm >> 9) + 2) * 1024;
            long long aoff = (ab + k0) * 2 + sg * 16;
            CP16(st + soff, (const char*)Ahi + aoff);
            if (NPASS == 3) CP16(st + A_OPB + soff, (const char*)Alo + aoff);
        }
        #pragma unroll
        for (int i2 = 0; i2 < 2; i2++) {      // B: 512 segs per operand
            int sidx = i2 * 256 + tid;
            int r = sidx >> 2, sg = sidx & 3;
            uint32_t soff = r * 80 + sg * 16;
            long long bb = ((long long)(n0 + r) * Kd + k0) * 2 + sg * 16;
            CP16(st + 2 * A_OPB + soff, (const char*)Bhi + bb);
            if (NPASS >= 2)
                CP16(st + 2 * A_OPB + B_OPB + soff, (const char*)Blo + bb);
        }
        CP_COMMIT();
    };

    load_chunk(0);
    if (nch > 1) load_chunk(1);
    for (int j = 0; j < nch; j++) {
        if (j + 2 < nch) { load_chunk(j + 2); cp_wait<2>(); }
        else if (j + 1 < nch) cp_wait<1>();
        else cp_wait<0>();
        __syncthreads();

        uint32_t sA  = sb + (j % 3) * STAGE;
        uint32_t sAl = sA + A_OPB, sB = sA + 2 * A_OPB, sBl = sB + B_OPB;
        #pragma unroll
        for (int kc = 0; kc < 32; kc += 16) {
            uint32_t aH[4][4], bH[8][2];
            #pragma unroll
            for (int mt = 0; mt < 4; mt++) {
                uint32_t ro = (uint32_t)(wm + mt * 16 + (lane & 15)) * 80
                            + (kc + (lane >> 4) * 8) * 2;
                ldsm4(aH[mt], sA + ro);
            }
            #pragma unroll
            for (int bt = 0; bt < 4; bt++) {
                uint32_t ro = (uint32_t)(wn + bt * 16 + (lane >> 4) * 8 + (lane & 7)) * 80
                            + (kc + ((lane >> 3) & 1) * 8) * 2;
                uint32_t t4[4];
                ldsm4(t4, sB + ro);
                bH[2 * bt][0] = t4[0]; bH[2 * bt][1] = t4[1];
                bH[2 * bt + 1][0] = t4[2]; bH[2 * bt + 1][1] = t4[3];
            }
            #pragma unroll
            for (int mt = 0; mt < 4; mt++)
                #pragma unroll
                for (int nt = 0; nt < 8; nt++)
                    mma16816(acc[mt][nt], aH[mt], bH[nt]);
            // HL pass: load Bl, reuse aH
            if (NPASS >= 2) {
                uint32_t bL[8][2];
                #pragma unroll
                for (int bt = 0; bt < 4; bt++) {
                    uint32_t ro = (uint32_t)(wn + bt * 16 + (lane >> 4) * 8 + (lane & 7)) * 80
                                + (kc + ((lane >> 3) & 1) * 8) * 2;
                    uint32_t t4[4];
                    ldsm4(t4, sBl + ro);
                    bL[2 * bt][0] = t4[0]; bL[2 * bt][1] = t4[1];
                    bL[2 * bt + 1][0] = t4[2]; bL[2 * bt + 1][1] = t4[3];
                }
                #pragma unroll
                for (int mt = 0; mt < 4; mt++)
                    #pragma unroll
                    for (int nt = 0; nt < 8; nt++)
                        mma16816(acc[mt][nt], aH[mt], bL[nt]);
            }
            // LH pass (NPASS==3): load Al, reuse bH
            if (NPASS == 3) {
                uint32_t aL[4][4];
                #pragma unroll
                for (int mt = 0; mt < 4; mt++) {
                    uint32_t ro = (uint32_t)(wm + mt * 16 + (lane & 15)) * 80
                                + (kc + (lane >> 4) * 8) * 2;
                    ldsm4(aL[mt], sAl + ro);
                }
                #pragma unroll
                for (int mt = 0; mt < 4; mt++)
                    #pragma unroll
                    for (int nt = 0; nt < 8; nt++)
                        mma16816(acc[mt][nt], aL[mt], bH[nt]);
            }
        }
        __syncthreads();
    }

    // ---- epilogue: fragment c0,c1 = row lane/4, c2,c3 = row+8 ----
    const int rq = lane >> 2, cq = (lane & 3) * 2;
    #pragma unroll
    for (int mt = 0; mt < 4; mt++) {
        #pragma unroll
        for (int h = 0; h < 2; h++) {
            int m = m0 + wm + mt * 16 + h * 8 + rq;
            long long crow;
            if (CMAP == 0) crow = (long long)m * N;
            else           crow = (long long)(m + 2 * (m >> 9) + 2) * 1024;
            long long arow = (long long)m * N;
            #pragma unroll
            for (int nt = 0; nt < 8; nt++) {
                int n = n0 + wn + nt * 8 + cq;
                float x = acc[mt][nt][h * 2 + 0];
                float y = acc[mt][nt][h * 2 + 1];
                if (EPI != 3) {
                    float2 b2 = *(const float2*)(bias + n);
                    x += b2.x; y += b2.y;
                }
                if (EPI == 1 || EPI == 2) {
                    float2 a2 = *(const float2*)(add1 + arow + n);
                    x = (x + a2.x) * SCALE; y = (y + a2.y) * SCALE;
                }
                if (EPI == 2) {
                    float2 c2v = *(const float2*)(C + crow + n);
                    x = (x + c2v.x) * SCALE; y = (y + c2v.y) * SCALE;
                }
                if (OUT != 2) { float2 o2; o2.x = x; o2.y = y;
                                *(float2*)(C + crow + n) = o2; }
                if (OUT >= 1) store_split2(Chi + crow + n, Clo + crow + n, x, y);
            }
        }
    }
}

// ===========================================================================
extern "C" void kernel_launch(void* const* d_in, const int* in_sizes, int n_in,
                              void* d_out, int out_size) {
    const int*   trg        = (const int*)d_in[0];
    const float* enc_conved = (const float*)d_in[1];
    const float* enc_comb   = (const float*)d_in[2];
    const float* tok_emb    = (const float*)d_in[3];
    const float* pos_emb    = (const float*)d_in[4];
    const float* emb2hid_w  = (const float*)d_in[5];
    const float* emb2hid_b  = (const float*)d_in[6];
    const float* hid2emb_w  = (const float*)d_in[7];
    const float* hid2emb_b  = (const float*)d_in[8];
    const float* attn_h2e_w = (const float*)d_in[9];
    const float* attn_h2e_b = (const float*)d_in[10];
    const float* attn_e2h_w = (const float*)d_in[11];
    const float* attn_e2h_b = (const float*)d_in[12];
    const float* fc_w       = (const float*)d_in[13];
    const float* fc_b       = (const float*)d_in[14];
    const float* conv_w     = (const float*)d_in[15];
    const float* conv_b     = (const float*)d_in[16];
    float* out = (float*)d_out;

    unsigned char* base = nullptr;
    cudaGetSymbolAddress((void**)&base, g_mem);
#define F32P(o) ((float*)(base + (o)))
#define HP(o)   ((__half*)(base + (o)))
    float *embF = F32P(oEMBF), *xpadF = F32P(oXPADF), *convF = F32P(oCONVF);
    float *gluF = F32P(oGLUF), *attnF = F32P(oATTNF);
    __half *embH = HP(oEMBH),  *embL = HP(oEMBL);
    __half *xpH  = HP(oXPADH), *xpL  = HP(oXPADL);
    __half *glH  = HP(oGLUH),  *glL  = HP(oGLUL);
    __half *cbH  = HP(oCOMBH), *cbL  = HP(oCOMBL);
    __half *atH  = HP(oATTNH), *atL  = HP(oATTNL);
    __half *adH  = HP(oATTH),  *adL  = HP(oATTL);
    __half *coH  = HP(oCOUTH), *coL  = HP(oCOUTL);
    __half *wtH  = HP(oWTH),   *wtL  = HP(oWTL);
    __half *w1H  = HP(oW1H),   *w1L  = HP(oW1L);
    __half *w2H  = HP(oW2H),   *w2L  = HP(oW2L);
    __half *w3H  = HP(oW3H),   *w3L  = HP(oW3L);
    __half *w4H  = HP(oW4H),   *w4L  = HP(oW4L);
    __half *wfH  = HP(oWFCH),  *wfL  = HP(oWFCL);
    __half *evH  = HP(oENCVH), *evL  = HP(oENCVL);
    __half *etH  = HP(oENCTH), *etL  = HP(oENCTL);

    cudaFuncSetAttribute(tgemm<0,1,0,1,3>, cudaFuncAttributeMaxDynamicSharedMemorySize, GSMEM);
    cudaFuncSetAttribute(tgemm<1,0,0,0,1>, cudaFuncAttributeMaxDynamicSharedMemorySize, GSMEM);
    cudaFuncSetAttribute(tgemm<1,0,0,0,2>, cudaFuncAttributeMaxDynamicSharedMemorySize, GSMEM);
    cudaFuncSetAttribute(tgemm<0,0,1,2,2>, cudaFuncAttributeMaxDynamicSharedMemorySize, GSMEM);
    cudaFuncSetAttribute(tgemm<0,0,3,0,2>, cudaFuncAttributeMaxDynamicSharedMemorySize, GSMEM);
    cudaFuncSetAttribute(tgemm<0,0,3,2,2>, cudaFuncAttributeMaxDynamicSharedMemorySize, GSMEM);
    cudaFuncSetAttribute(tgemm<0,1,2,1,2>, cudaFuncAttributeMaxDynamicSharedMemorySize, GSMEM);
    cudaFuncSetAttribute(tgemm<2,0,0,2,3>, cudaFuncAttributeMaxDynamicSharedMemorySize, GSMEM);
    cudaFuncSetAttribute(tgemm<0,0,0,0,2>, cudaFuncAttributeMaxDynamicSharedMemorySize, GSMEM);

    const long long TS = (long long)TLEN * TLEN;  // 262144

    // ---- one-time prep ----
    embed_kernel<<<MTOT, 128>>>(trg, tok_emb, pos_emb, embF, embH, embL);
    pad_kernel<<<16, 1024>>>(xpadF, xpH, xpL);
    transpose_split_kernel<<<dim3(32, 16), dim3(32, 8)>>>(emb2hid_w, w1H, w1L, 512, 1024, 0);
    transpose_split_kernel<<<dim3(16, 32), dim3(32, 8)>>>(attn_h2e_w, w2H, w2L, 1024, 512, 0);
    transpose_split_kernel<<<dim3(32, 16), dim3(32, 8)>>>(attn_e2h_w, w3H, w3L, 512, 1024, 0);
    transpose_split_kernel<<<dim3(16, 32), dim3(32, 8)>>>(hid2emb_w, w4H, w4L, 1024, 512, 0);
    transpose_split_kernel<<<dim3(1000, 16), dim3(32, 8)>>>(fc_w, wfH, wfL, 512, 32000, 0);
    transpose_split_kernel<<<dim3(16, 16, 8), dim3(32, 8)>>>(enc_comb, etH, etL, 512, 512, TS);
    split_kernel<<<8192, 256>>>(enc_conved, evH, evL, 2097152LL);

    // conv_input = embedded @ emb2hid + b -> xpad (fp32 + split), 3-pass
    tgemm<0,1,0,1,3><<<dim3(8, 16), 256, GSMEM>>>(
        embH, embL, w1H, w1L, emb2hid_b, nullptr, xpadF, xpH, xpL,
        1024, 512, 512, 0, 0, 0);

    for (int l = 0; l < NL; l++) {
        convw_split_kernel<<<2048, 256>>>(conv_w + (long long)l * 2048 * 3072, wtH, wtL);

        // conved = xpad(conv map) @ wt^T + b  (K=3072), fp32 only.
        // Layers 0-4: 1-pass (deep damping); layer 5: 2-pass.
        if (l < NL - 1)
            tgemm<1,0,0,0,1><<<dim3(16, 16), 256, GSMEM>>>(
                xpH, xpL, wtH, wtL, conv_b + l * 2048, nullptr, convF, nullptr, nullptr,
                2048, 3072, 1024, 0, 0, 0);
        else
            tgemm<1,0,0,0,2><<<dim3(16, 16), 256, GSMEM>>>(
                xpH, xpL, wtH, wtL, conv_b + l * 2048, nullptr, convF, nullptr, nullptr,
                2048, 3072, 1024, 0, 0, 0);

        glu_kernel<<<4096, 1024>>>(convF, gluF, glH, glL);

        // combined = (glu @ h2e + b + emb)*scale, split only, 2-pass
        tgemm<0,0,1,2,2><<<dim3(4, 16), 256, GSMEM>>>(
            glH, glL, w2H, w2L, attn_h2e_b, embF, nullptr, cbH, cbL,
            512, 1024, 1024, 0, 0, 0);

        // energy = combined @ enc_conved^T (batched), fp32 only, 2-pass
        tgemm<0,0,3,0,2><<<dim3(4, 2, 8), 256, GSMEM>>>(
            cbH, cbL, evH, evL, nullptr, nullptr, attnF, nullptr, nullptr,
            512, 512, 512, TS, TS, TS);

        softmax_kernel<<<MTOT, 128>>>(attnF, atH, atL);

        // attended = attn @ enc_combined (batched, B = enc_comb^T), split only, 2-pass
        tgemm<0,0,3,2,2><<<dim3(4, 2, 8), 256, GSMEM>>>(
            atH, atL, etH, etL, nullptr, nullptr, nullptr, adH, adL,
            512, 512, 512, TS, TS, TS);

        // conv_input = ((attended@e2h + b + glu)*S + conv_input)*S -> xpad, 2-pass
        tgemm<0,1,2,1,2><<<dim3(8, 16), 256, GSMEM>>>(
            adH, adL, w3H, w3L, attn_e2h_b, gluF, xpadF, xpH, xpL,
            1024, 512, 512, 0, 0, 0);
    }

    // conv_output = conv_input(token map) @ hid2emb + b, split only, 3-pass
    // (undamped path to logits -- keep high precision)
    tgemm<2,0,0,2,3><<<dim3(4, 16), 256, GSMEM>>>(
        xpH, xpL, w4H, w4L, hid2emb_b, nullptr, nullptr, coH, coL,
        512, 1024, 1024, 0, 0, 0);

    // logits = conv_output @ fc + b, fp32 -> d_out, 2-pass
    tgemm<0,0,0,0,2><<<dim3(250, 16), 256, GSMEM>>>(
        coH, coL, wfH, wfL, fc_b, nullptr, out, nullptr, nullptr,
        32000, 512, 512, 0, 0, 0);
}

// round 16
// speedup vs baseline: 1.7359x; 1.7359x over previous
#include <cuda_runtime.h>
#include <cuda_fp16.h>
#include <cstdint>
#include <math.h>

#define BATCH 8
#define TLEN 512
#define EDIM 512
#define HDIM 1024
#define VDIM 32000
#define NL 6
#define MTOT (BATCH*TLEN)
#define SCALE 0.7071067811865476f

// ===========================================================================
// Scratch carve-out (bytes)
// ===========================================================================
constexpr unsigned long long
 oEMBF  = 0ull,
 oXPADF = oEMBF  + 8388608ull,
 oCONVF = oXPADF + 16842752ull,
 oGLUF  = oCONVF + 33554432ull,
 oATTNF = oGLUF  + 16777216ull,
 oEMBH  = oATTNF + 8388608ull,
 oEMBL  = oEMBH  + 4194304ull,
 oXPADH = oEMBL  + 4194304ull,
 oXPADL = oXPADH + 8421376ull,
 oGLUH  = oXPADL + 8421376ull,
 oGLUL  = oGLUH  + 8388608ull,
 oCOMBH = oGLUL  + 8388608ull,
 oCOMBL = oCOMBH + 4194304ull,
 oATTNH = oCOMBL + 4194304ull,
 oATTNL = oATTNH + 4194304ull,
 oATTH  = oATTNL + 4194304ull,
 oATTL  = oATTH  + 4194304ull,
 oCOUTH = oATTL  + 4194304ull,
 oCOUTL = oCOUTH + 4194304ull,
 oWTH   = oCOUTL + 4194304ull,
 oWTL   = oWTH   + 12582912ull,
 oW1H   = oWTL   + 12582912ull,
 oW1L   = oW1H   + 1048576ull,
 oW2H   = oW1L   + 1048576ull,
 oW2L   = oW2H   + 1048576ull,
 oW3H   = oW2L   + 1048576ull,
 oW3L   = oW3H   + 1048576ull,
 oW4H   = oW3L   + 1048576ull,
 oW4L   = oW4H   + 1048576ull,
 oWFCH  = oW4L   + 1048576ull,
 oWFCL  = oWFCH  + 32768000ull,
 oENCVH = oWFCL  + 32768000ull,
 oENCVL = oENCVH + 4194304ull,
 oENCTH = oENCVL + 4194304ull,
 oENCTL = oENCTH + 4194304ull,
 G_TOTAL = oENCTL + 4194304ull;

__device__ __align__(1024) unsigned char g_mem[G_TOTAL];

// ===========================================================================
// PTX helpers (arch-agnostic: cp.async + ldmatrix + mma.sync fp16)
// ===========================================================================
__device__ __forceinline__ uint32_t smem_u32(const void* p) {
    uint32_t a;
    asm("{ .reg .u64 t; cvta.to.shared.u64 t, %1; cvt.u32.u64 %0, t; }" : "=r"(a) : "l"(p));
    return a;
}
#define CP16(dst, src) asm volatile("cp.async.cg.shared.global [%0], [%1], 16;" :: "r"(dst), "l"(src))
#define CP_COMMIT()    asm volatile("cp.async.commit_group;" ::: "memory")
template<int N> __device__ __forceinline__ void cp_wait() {
    asm volatile("cp.async.wait_group %0;" :: "n"(N) : "memory");
}
__device__ __forceinline__ void ldsm4(uint32_t* d, uint32_t a) {
    asm volatile("ldmatrix.sync.aligned.m8n8.x4.shared.b16 {%0,%1,%2,%3}, [%4];"
        : "=r"(d[0]), "=r"(d[1]), "=r"(d[2]), "=r"(d[3]) : "r"(a));
}
__device__ __forceinline__ void mma16816(float* c, const uint32_t* a, const uint32_t* b) {
    asm volatile("mma.sync.aligned.m16n8k16.row.col.f32.f16.f16.f32 "
        "{%0,%1,%2,%3}, {%4,%5,%6,%7}, {%8,%9}, {%0,%1,%2,%3};"
        : "+f"(c[0]), "+f"(c[1]), "+f"(c[2]), "+f"(c[3])
        : "r"(a[0]), "r"(a[1]), "r"(a[2]), "r"(a[3]), "r"(b[0]), "r"(b[1]));
}

__device__ __forceinline__ void store_split4(__half* ph, __half* pl, float4 v) {
    __half h0 = __float2half_rn(v.x), h1 = __float2half_rn(v.y);
    __half h2 = __float2half_rn(v.z), h3 = __float2half_rn(v.w);
    __half2 a; a.x = h0; a.y = h1;
    __half2 b; b.x = h2; b.y = h3;
    *(__half2*)(ph) = a; *(__half2*)(ph + 2) = b;
    __half2 c, d;
    c.x = __float2half_rn(v.x - __half2float(h0));
    c.y = __float2half_rn(v.y - __half2float(h1));
    d.x = __float2half_rn(v.z - __half2float(h2));
    d.y = __float2half_rn(v.w - __half2float(h3));
    *(__half2*)(pl) = c; *(__half2*)(pl + 2) = d;
}
__device__ __forceinline__ void store_split2(__half* ph, __half* pl, float x, float y) {
    __half h0 = __float2half_rn(x), h1 = __float2half_rn(y);
    __half2 a; a.x = h0; a.y = h1;
    *(__half2*)(ph) = a;
    __half2 c;
    c.x = __float2half_rn(x - __half2float(h0));
    c.y = __float2half_rn(y - __half2float(h1));
    *(__half2*)(pl) = c;
}

// ===========================================================================
// Elementwise / prep kernels
// ===========================================================================
__global__ void embed_kernel(const int* __restrict__ trg, const float* __restrict__ tok,
                             const float* __restrict__ pos, float* __restrict__ out,
                             __half* __restrict__ oh, __half* __restrict__ ol) {
    int m = blockIdx.x, t = m & (TLEN - 1), i = threadIdx.x;
    long long tokid = trg[m];
    float4 a = ((const float4*)(tok + tokid * EDIM))[i];
    float4 b = ((const float4*)(pos + (long long)t * EDIM))[i];
    float4 v = make_float4(a.x + b.x, a.y + b.y, a.z + b.z, a.w + b.w);
    ((float4*)(out + (long long)m * EDIM))[i] = v;
    long long o = (long long)m * EDIM + i * 4;
    store_split4(oh + o, ol + o, v);
}

__global__ void pad_kernel(float* __restrict__ xp, __half* __restrict__ xh,
                           __half* __restrict__ xl) {
    int i = blockIdx.x * blockDim.x + threadIdx.x;
    int b = i >> 11, r = i & 2047;
    long long o = (long long)b * 514 * 1024 + r;
    xp[o] = 1.0f; xh[o] = __float2half_rn(1.0f); xl[o] = __float2half_rn(0.0f);
}

__global__ void glu_kernel(const float* __restrict__ conved, float* __restrict__ out,
                           __half* __restrict__ oh, __half* __restrict__ ol) {
    long long idx = (long long)blockIdx.x * blockDim.x + threadIdx.x;
    long long m = idx >> 10;
    int j = (int)(idx & 1023);
    float a = conved[m * 2048 + j];
    float g = conved[m * 2048 + 1024 + j];
    float v = a * (1.0f / (1.0f + expf(-g)));
    out[idx] = v;
    __half h = __float2half_rn(v);
    oh[idx] = h;
    ol[idx] = __float2half_rn(v - __half2float(h));
}

__global__ void softmax_kernel(const float* __restrict__ attn,
                               __half* __restrict__ oh, __half* __restrict__ ol) {
    long long row = blockIdx.x;
    const float4* p = (const float4*)(attn + row * 512);
    float4 v = p[threadIdx.x];
    float mx = fmaxf(fmaxf(v.x, v.y), fmaxf(v.z, v.w));
    #pragma unroll
    for (int s = 16; s; s >>= 1) mx = fmaxf(mx, __shfl_xor_sync(0xffffffffu, mx, s));
    __shared__ float sm[4], ss[4];
    int w = threadIdx.x >> 5;
    if ((threadIdx.x & 31) == 0) sm[w] = mx;
    __syncthreads();
    mx = fmaxf(fmaxf(sm[0], sm[1]), fmaxf(sm[2], sm[3]));
    v.x = expf(v.x - mx); v.y = expf(v.y - mx);
    v.z = expf(v.z - mx); v.w = expf(v.w - mx);
    float sum = v.x + v.y + v.z + v.w;
    #pragma unroll
    for (int s = 16; s; s >>= 1) sum += __shfl_xor_sync(0xffffffffu, sum, s);
    if ((threadIdx.x & 31) == 0) ss[w] = sum;
    __syncthreads();
    float inv = 1.0f / (ss[0] + ss[1] + ss[2] + ss[3]);
    v.x *= inv; v.y *= inv; v.z *= inv; v.w *= inv;
    long long o = row * 512 + threadIdx.x * 4;
    store_split4(oh + o, ol + o, v);
}

__global__ void split_kernel(const float* __restrict__ in, __half* __restrict__ oh,
                             __half* __restrict__ ol, long long n) {
    long long idx = (long long)blockIdx.x * blockDim.x + threadIdx.x;
    if (idx >= n) return;
    float v = in[idx];
    __half h = __float2half_rn(v);
    oh[idx] = h;
    ol[idx] = __float2half_rn(v - __half2float(h));
}

// fp32 (R,C) -> fp16 hi/lo (C,R), batched by blockIdx.z
__global__ void transpose_split_kernel(const float* __restrict__ in,
                                       __half* __restrict__ oh,
                                       __half* __restrict__ ol,
                                       int R, int C, long long bat) {
    __shared__ float t[32][33];
    in += blockIdx.z * bat; oh += blockIdx.z * bat; ol += blockIdx.z * bat;
    int c0 = blockIdx.x * 32, r0 = blockIdx.y * 32;
    int tx = threadIdx.x, ty = threadIdx.y;
    for (int ry = ty; ry < 32; ry += 8)
        t[ry][tx] = in[(long long)(r0 + ry) * C + c0 + tx];
    __syncthreads();
    for (int ry = ty; ry < 32; ry += 8) {
        float v = t[tx][ry];
        long long o = (long long)(c0 + ry) * R + r0 + tx;
        __half h = __float2half_rn(v);
        oh[o] = h;
        ol[o] = __float2half_rn(v - __half2float(h));
    }
}

// conv_w layer (2H,H,K): row o contiguous (i,kk); out[o][kk*1024+i], split.
__global__ void convw_split_kernel(const float* __restrict__ w,
                                   __half* __restrict__ oh,
                                   __half* __restrict__ ol) {
    __shared__ float row[3072];
    long long o = blockIdx.x;
    for (int x = threadIdx.x; x < 3072; x += 256) row[x] = w[o * 3072 + x];
    __syncthreads();
    for (int y = threadIdx.x; y < 3072; y += 256) {
        int i = y & 1023, kk = y >> 10;
        float v = row[i * 3 + kk];
        __half h = __float2half_rn(v);
        oh[o * 3072 + y] = h;
        ol[o * 3072 + y] = __float2half_rn(v - __half2float(h));
    }
}

// ===========================================================================
// mma.sync fp16-split GEMM: C(256x128 tile) = epi( A(M,K) @ B(N,K)^T )
//   NPASS=3: Ah*Bh + Ah*Bl + Al*Bh   (error ~ eps_fp16^2)
//   NPASS=2: Ah*Bh + Ah*Bl           (A rounded; error ~ eps_fp16/sqrt(3))
//   NPASS=1: Ah*Bh                   (both rounded; deeply damped only)
//   Stage holds only the operands NPASS needs, so pipeline depth adapts:
//   NPASS=3 -> 3 stages, NPASS=2 -> 4 stages, NPASS=1 -> 6 stages (184KB).
//   256 threads, 8 warps (4x2 -> 64x64 per warp), BK=32.
//   Smem rows padded to 40 halves (80B) -> conflict-free ldmatrix.
//   AMAP: 0 row m*lda ; 1 conv map (m+2b)*1024 ; 2 token map (m+2b+2)*1024
//   CMAP: 0 m*N ; 1 xpad interior
//   EPI : 0 +bias ; 1 (acc+b+add1)*S ; 2 ((acc+b+add1)*S+Cold)*S ; 3 plain
//   OUT : 0 fp32 ; 1 fp32+split ; 2 split only
// ===========================================================================
constexpr int A_OPB  = 256 * 80;   // 20480 B per A operand
constexpr int B_OPB  = 128 * 80;   // 10240 B per B operand
constexpr int GSMEM  = 184320;     // total dynamic smem for all variants

template<int AMAP, int CMAP, int EPI, int OUT, int NPASS>
__global__ __launch_bounds__(256, 1) void tgemm(
    const __half* __restrict__ Ahi, const __half* __restrict__ Alo,
    const __half* __restrict__ Bhi, const __half* __restrict__ Blo,
    const float* __restrict__ bias, const float* __restrict__ add1,
    float* __restrict__ C, __half* __restrict__ Chi, __half* __restrict__ Clo,
    int N, int Kd, int lda, long long batA, long long batB, long long batC)
{
    constexpr int SA   = A_OPB * (NPASS == 3 ? 2 : 1);
    constexpr int SB   = B_OPB * (NPASS >= 2 ? 2 : 1);
    constexpr int STG  = SA + SB;
    constexpr int NSTG = GSMEM / STG;   // 3 / 4 / 6

    extern __shared__ __align__(128) char smem[];
    const uint32_t sb = smem_u32(smem);
    const int tid = threadIdx.x;
    const int lane = tid & 31, wid = tid >> 5;
    const int m0 = blockIdx.y * 256, n0 = blockIdx.x * 128;
    const int wm = (wid >> 1) * 64, wn = (wid & 1) * 64;
    {
        long long z = blockIdx.z;
        Ahi += z * batA; Alo += z * batA;
        Bhi += z * batB; Blo += z * batB;
        if (OUT != 2) C += z * batC;
        if (OUT >= 1) { Chi += z * batC; Clo += z * batC; }
    }

    float acc[4][8][4];
    #pragma unroll
    for (int a = 0; a < 4; a++)
        #pragma unroll
        for (int b = 0; b < 8; b++)
            #pragma unroll
            for (int c = 0; c < 4; c++) acc[a][b][c] = 0.0f;

    const int nch = Kd >> 5;   // BK = 32

    auto load_chunk = [&](int j) {
        uint32_t st = sb + (j % NSTG) * STG;
        int k0 = j * 32;
        #pragma unroll
        for (int i2 = 0; i2 < 4; i2++) {      // A: 1024 16B-segs per operand
            int sidx = i2 * 256 + tid;
            int r = sidx >> 2, sg = sidx & 3;
            uint32_t soff = r * 80 + sg * 16;
            int gm = m0 + r;
            long long ab;
            if (AMAP == 0)      ab = (long long)gm * lda;
            else if (AMAP == 1) ab = (long long)(gm + 2 * (gm >> 9)) * 1024;
            else                ab = (long long)(gm + 2 * (gm >> 9) + 2) * 1024;
            long long aoff = (ab + k0) * 2 + sg * 16;
            CP16(st + soff, (const char*)Ahi + aoff);
            if (NPASS == 3) CP16(st + A_OPB + soff, (const char*)Alo + aoff);
        }
        #pragma unroll
        for (int i2 = 0; i2 < 2; i2++) {      // B: 512 segs per operand
            int sidx = i2 * 256 + tid;
            int r = sidx >> 2, sg = sidx & 3;
            uint32_t soff = r * 80 + sg * 16;
            long long bb = ((long long)(n0 + r) * Kd + k0) * 2 + sg * 16;
            CP16(st + SA + soff, (const char*)Bhi + bb);
            if (NPASS >= 2)
                CP16(st + SA + B_OPB + soff, (const char*)Blo + bb);
        }
        CP_COMMIT();
    };

    // prologue: keep NSTG-1 chunks in flight
    for (int p = 0; p < NSTG - 1 && p < nch; p++) load_chunk(p);

    for (int j = 0; j < nch; j++) {
        if (j + NSTG - 1 < nch) load_chunk(j + NSTG - 1);
        // wait until chunk j is resident: allow (pending-1) groups to remain
        int rem = nch - 1 - j;
        if (rem > NSTG - 1) rem = NSTG - 1;
        if      (rem >= 5) cp_wait<5>();
        else if (rem == 4) cp_wait<4>();
        else if (rem == 3) cp_wait<3>();
        else if (rem == 2) cp_wait<2>();
        else if (rem == 1) cp_wait<1>();
        else               cp_wait<0>();
        __syncthreads();

        uint32_t sA  = sb + (j % NSTG) * STG;
        uint32_t sAl = sA + A_OPB;         // valid only NPASS==3
        uint32_t sB  = sA + SA;
        uint32_t sBl = sB + B_OPB;         // valid only NPASS>=2
        #pragma unroll
        for (int kc = 0; kc < 32; kc += 16) {
            uint32_t aH[4][4], bH[8][2];
            #pragma unroll
            for (int mt = 0; mt < 4; mt++) {
                uint32_t ro = (uint32_t)(wm + mt * 16 + (lane & 15)) * 80
                            + (kc + (lane >> 4) * 8) * 2;
                ldsm4(aH[mt], sA + ro);
            }
            #pragma unroll
            for (int bt = 0; bt < 4; bt++) {
                uint32_t ro = (uint32_t)(wn + bt * 16 + (lane >> 4) * 8 + (lane & 7)) * 80
                            + (kc + ((lane >> 3) & 1) * 8) * 2;
                uint32_t t4[4];
                ldsm4(t4, sB + ro);
                bH[2 * bt][0] = t4[0]; bH[2 * bt][1] = t4[1];
                bH[2 * bt + 1][0] = t4[2]; bH[2 * bt + 1][1] = t4[3];
            }
            #pragma unroll
            for (int mt = 0; mt < 4; mt++)
                #pragma unroll
                for (int nt = 0; nt < 8; nt++)
                    mma16816(acc[mt][nt], aH[mt], bH[nt]);
            // HL pass: load Bl, reuse aH
            if (NPASS >= 2) {
                uint32_t bL[8][2];
                #pragma unroll
                for (int bt = 0; bt < 4; bt++) {
                    uint32_t ro = (uint32_t)(wn + bt * 16 + (lane >> 4) * 8 + (lane & 7)) * 80
                                + (kc + ((lane >> 3) & 1) * 8) * 2;
                    uint32_t t4[4];
                    ldsm4(t4, sBl + ro);
                    bL[2 * bt][0] = t4[0]; bL[2 * bt][1] = t4[1];
                    bL[2 * bt + 1][0] = t4[2]; bL[2 * bt + 1][1] = t4[3];
                }
                #pragma unroll
                for (int mt = 0; mt < 4; mt++)
                    #pragma unroll
                    for (int nt = 0; nt < 8; nt++)
                        mma16816(acc[mt][nt], aH[mt], bL[nt]);
            }
            // LH pass (NPASS==3): load Al, reuse bH
            if (NPASS == 3) {
                uint32_t aL[4][4];
                #pragma unroll
                for (int mt = 0; mt < 4; mt++) {
                    uint32_t ro = (uint32_t)(wm + mt * 16 + (lane & 15)) * 80
                                + (kc + (lane >> 4) * 8) * 2;
                    ldsm4(aL[mt], sAl + ro);
                }
                #pragma unroll
                for (int mt = 0; mt < 4; mt++)
                    #pragma unroll
                    for (int nt = 0; nt < 8; nt++)
                        mma16816(acc[mt][nt], aL[mt], bH[nt]);
            }
        }
        __syncthreads();
    }

    // ---- epilogue: fragment c0,c1 = row lane/4, c2,c3 = row+8 ----
    const int rq = lane >> 2, cq = (lane & 3) * 2;
    #pragma unroll
    for (int mt = 0; mt < 4; mt++) {
        #pragma unroll
        for (int h = 0; h < 2; h++) {
            int m = m0 + wm + mt * 16 + h * 8 + rq;
            long long crow;
            if (CMAP == 0) crow = (long long)m * N;
            else           crow = (long long)(m + 2 * (m >> 9) + 2) * 1024;
            long long arow = (long long)m * N;
            #pragma unroll
            for (int nt = 0; nt < 8; nt++) {
                int n = n0 + wn + nt * 8 + cq;
                float x = acc[mt][nt][h * 2 + 0];
                float y = acc[mt][nt][h * 2 + 1];
                if (EPI != 3) {
                    float2 b2 = *(const float2*)(bias + n);
                    x += b2.x; y += b2.y;
                }
                if (EPI == 1 || EPI == 2) {
                    float2 a2 = *(const float2*)(add1 + arow + n);
                    x = (x + a2.x) * SCALE; y = (y + a2.y) * SCALE;
                }
                if (EPI == 2) {
                    float2 c2v = *(const float2*)(C + crow + n);
                    x = (x + c2v.x) * SCALE; y = (y + c2v.y) * SCALE;
                }
                if (OUT != 2) { float2 o2; o2.x = x; o2.y = y;
                                *(float2*)(C + crow + n) = o2; }
                if (OUT >= 1) store_split2(Chi + crow + n, Clo + crow + n, x, y);
            }
        }
    }
}

// ===========================================================================
extern "C" void kernel_launch(void* const* d_in, const int* in_sizes, int n_in,
                              void* d_out, int out_size) {
    const int*   trg        = (const int*)d_in[0];
    const float* enc_conved = (const float*)d_in[1];
    const float* enc_comb   = (const float*)d_in[2];
    const float* tok_emb    = (const float*)d_in[3];
    const float* pos_emb    = (const float*)d_in[4];
    const float* emb2hid_w  = (const float*)d_in[5];
    const float* emb2hid_b  = (const float*)d_in[6];
    const float* hid2emb_w  = (const float*)d_in[7];
    const float* hid2emb_b  = (const float*)d_in[8];
    const float* attn_h2e_w = (const float*)d_in[9];
    const float* attn_h2e_b = (const float*)d_in[10];
    const float* attn_e2h_w = (const float*)d_in[11];
    const float* attn_e2h_b = (const float*)d_in[12];
    const float* fc_w       = (const float*)d_in[13];
    const float* fc_b       = (const float*)d_in[14];
    const float* conv_w     = (const float*)d_in[15];
    const float* conv_b     = (const float*)d_in[16];
    float* out = (float*)d_out;

    unsigned char* base = nullptr;
    cudaGetSymbolAddress((void**)&base, g_mem);
#define F32P(o) ((float*)(base + (o)))
#define HP(o)   ((__half*)(base + (o)))
    float *embF = F32P(oEMBF), *xpadF = F32P(oXPADF), *convF = F32P(oCONVF);
    float *gluF = F32P(oGLUF), *attnF = F32P(oATTNF);
    __half *embH = HP(oEMBH),  *embL = HP(oEMBL);
    __half *xpH  = HP(oXPADH), *xpL  = HP(oXPADL);
    __half *glH  = HP(oGLUH),  *glL  = HP(oGLUL);
    __half *cbH  = HP(oCOMBH), *cbL  = HP(oCOMBL);
    __half *atH  = HP(oATTNH), *atL  = HP(oATTNL);
    __half *adH  = HP(oATTH),  *adL  = HP(oATTL);
    __half *coH  = HP(oCOUTH), *coL  = HP(oCOUTL);
    __half *wtH  = HP(oWTH),   *wtL  = HP(oWTL);
    __half *w1H  = HP(oW1H),   *w1L  = HP(oW1L);
    __half *w2H  = HP(oW2H),   *w2L  = HP(oW2L);
    __half *w3H  = HP(oW3H),   *w3L  = HP(oW3L);
    __half *w4H  = HP(oW4H),   *w4L  = HP(oW4L);
    __half *wfH  = HP(oWFCH),  *wfL  = HP(oWFCL);
    __half *evH  = HP(oENCVH), *evL  = HP(oENCVL);
    __half *etH  = HP(oENCTH), *etL  = HP(oENCTL);

    cudaFuncSetAttribute(tgemm<0,1,0,1,3>, cudaFuncAttributeMaxDynamicSharedMemorySize, GSMEM);
    cudaFuncSetAttribute(tgemm<1,0,0,0,1>, cudaFuncAttributeMaxDynamicSharedMemorySize, GSMEM);
    cudaFuncSetAttribute(tgemm<1,0,0,0,2>, cudaFuncAttributeMaxDynamicSharedMemorySize, GSMEM);
    cudaFuncSetAttribute(tgemm<0,0,1,2,2>, cudaFuncAttributeMaxDynamicSharedMemorySize, GSMEM);
    cudaFuncSetAttribute(tgemm<0,0,3,0,2>, cudaFuncAttributeMaxDynamicSharedMemorySize, GSMEM);
    cudaFuncSetAttribute(tgemm<0,0,3,2,2>, cudaFuncAttributeMaxDynamicSharedMemorySize, GSMEM);
    cudaFuncSetAttribute(tgemm<0,1,2,1,2>, cudaFuncAttributeMaxDynamicSharedMemorySize, GSMEM);
    cudaFuncSetAttribute(tgemm<2,0,0,2,3>, cudaFuncAttributeMaxDynamicSharedMemorySize, GSMEM);
    cudaFuncSetAttribute(tgemm<0,0,0,0,2>, cudaFuncAttributeMaxDynamicSharedMemorySize, GSMEM);

    const long long TS = (long long)TLEN * TLEN;  // 262144

    // ---- one-time prep ----
    embed_kernel<<<MTOT, 128>>>(trg, tok_emb, pos_emb, embF, embH, embL);
    pad_kernel<<<16, 1024>>>(xpadF, xpH, xpL);
    transpose_split_kernel<<<dim3(32, 16), dim3(32, 8)>>>(emb2hid_w, w1H, w1L, 512, 1024, 0);
    transpose_split_kernel<<<dim3(16, 32), dim3(32, 8)>>>(attn_h2e_w, w2H, w2L, 1024, 512, 0);
    transpose_split_kernel<<<dim3(32, 16), dim3(32, 8)>>>(attn_e2h_w, w3H, w3L, 512, 1024, 0);
    transpose_split_kernel<<<dim3(16, 32), dim3(32, 8)>>>(hid2emb_w, w4H, w4L, 1024, 512, 0);
    transpose_split_kernel<<<dim3(1000, 16), dim3(32, 8)>>>(fc_w, wfH, wfL, 512, 32000, 0);
    transpose_split_kernel<<<dim3(16, 16, 8), dim3(32, 8)>>>(enc_comb, etH, etL, 512, 512, TS);
    split_kernel<<<8192, 256>>>(enc_conved, evH, evL, 2097152LL);

    // conv_input = embedded @ emb2hid + b -> xpad (fp32 + split), 3-pass
    tgemm<0,1,0,1,3><<<dim3(8, 16), 256, GSMEM>>>(
        embH, embL, w1H, w1L, emb2hid_b, nullptr, xpadF, xpH, xpL,
        1024, 512, 512, 0, 0, 0);

    for (int l = 0; l < NL; l++) {
        convw_split_kernel<<<2048, 256>>>(conv_w + (long long)l * 2048 * 3072, wtH, wtL);

        // conved = xpad(conv map) @ wt^T + b  (K=3072), fp32 only.
        // Layers 0-4: 1-pass (deep damping, 6-stage pipe); layer 5: 2-pass.
        if (l < NL - 1)
            tgemm<1,0,0,0,1><<<dim3(16, 16), 256, GSMEM>>>(
                xpH, xpL, wtH, wtL, conv_b + l * 2048, nullptr, convF, nullptr, nullptr,
                2048, 3072, 1024, 0, 0, 0);
        else
            tgemm<1,0,0,0,2><<<dim3(16, 16), 256, GSMEM>>>(
                xpH, xpL, wtH, wtL, conv_b + l * 2048, nullptr, convF, nullptr, nullptr,
                2048, 3072, 1024, 0, 0, 0);

        glu_kernel<<<4096, 1024>>>(convF, gluF, glH, glL);

        // combined = (glu @ h2e + b + emb)*scale, split only, 2-pass
        tgemm<0,0,1,2,2><<<dim3(4, 16), 256, GSMEM>>>(
            glH, glL, w2H, w2L, attn_h2e_b, embF, nullptr, cbH, cbL,
            512, 1024, 1024, 0, 0, 0);

        // energy = combined @ enc_conved^T (batched), fp32 only, 2-pass
        tgemm<0,0,3,0,2><<<dim3(4, 2, 8), 256, GSMEM>>>(
            cbH, cbL, evH, evL, nullptr, nullptr, attnF, nullptr, nullptr,
            512, 512, 512, TS, TS, TS);

        softmax_kernel<<<MTOT, 128>>>(attnF, atH, atL);

        // attended = attn @ enc_combined (batched, B = enc_comb^T), split only, 2-pass
        tgemm<0,0,3,2,2><<<dim3(4, 2, 8), 256, GSMEM>>>(
            atH, atL, etH, etL, nullptr, nullptr, nullptr, adH, adL,
            512, 512, 512, TS, TS, TS);

        // conv_input = ((attended@e2h + b + glu)*S + conv_input)*S -> xpad, 2-pass
        tgemm<0,1,2,1,2><<<dim3(8, 16), 256, GSMEM>>>(
            adH, adL, w3H, w3L, attn_e2h_b, gluF, xpadF, xpH, xpL,
            1024, 512, 512, 0, 0, 0);
    }

    // conv_output = conv_input(token map) @ hid2emb + b, split only, 3-pass
    tgemm<2,0,0,2,3><<<dim3(4, 16), 256, GSMEM>>>(
        xpH, xpL, w4H, w4L, hid2emb_b, nullptr, nullptr, coH, coL,
        512, 1024, 1024, 0, 0, 0);

    // logits = conv_output @ fc + b, fp32 -> d_out, 2-pass
    tgemm<0,0,0,0,2><<<dim3(250, 16), 256, GSMEM>>>(
        coH, coL, wfH, wfL, fc_b, nullptr, out, nullptr, nullptr,
        32000, 512, 512, 0, 0, 0);
}